// round 12
// baseline (speedup 1.0000x reference)
#include <cuda_runtime.h>
#include <cstring>

#define B_SZ   1024
#define S_SZ   2048
#define F_SZ   9
#define LB_SZ  3
#define T_STEPS 2044   // S - 1 - LB
#define LN_EPS 1e-3f
#define NTHR   512

// Partial pools: col-groups of 8 cols padded to 68 floats (64 data + 4 pad)
// so partial STS.128 lane-stride is 68 words (4 mod 32) -> conflict-free.
#define P16 2176                 // 32 groups * 68  (N=256 GEMMs, 16 slices)
#define P8  4352                 // 64 groups * 68  (N=512 dec1, 8 slices)
#define POOL_FLOATS 34816        // max(16*P16, 8*P8)
#define POOL_BYTES  (POOL_FLOATS * 4)

extern __shared__ float pool[];  // 136 KB dynamic scratch (GEMM partials)

// ---------------------------------------------------------------------------
// Packed fp32x2 FMA (Blackwell FFMA2) — only reachable via PTX fma.rn.f32x2
// ---------------------------------------------------------------------------
__device__ __forceinline__ float2 ffma2(float2 a, float2 b, float2 c) {
    unsigned long long ra, rb, rc, rd;
    memcpy(&ra, &a, 8); memcpy(&rb, &b, 8); memcpy(&rc, &c, 8);
    asm("fma.rn.f32x2 %0, %1, %2, %3;" : "=l"(rd) : "l"(ra), "l"(rb), "l"(rc));
    float2 d; memcpy(&d, &rd, 8);
    return d;
}

__device__ __forceinline__ float4 ld4(const float* p) {
    return *reinterpret_cast<const float4*>(p);
}

// One k-row: 8 cols x 8 rows = 32 FFMA2. Arow = 8 activation floats (SMEM).
__device__ __forceinline__ void fma8x1(float2 (&acc)[8][4],
                                       const float* __restrict__ Arow,
                                       float4 wlo, float4 whi)
{
    float4 aA = ld4(Arow);
    float4 aB = ld4(Arow + 4);
    float2 r0 = make_float2(aA.x, aA.y), r1 = make_float2(aA.z, aA.w);
    float2 r2 = make_float2(aB.x, aB.y), r3 = make_float2(aB.z, aB.w);
    const float wv[8] = { wlo.x, wlo.y, wlo.z, wlo.w,
                          whi.x, whi.y, whi.z, whi.w };
#pragma unroll
    for (int c = 0; c < 8; ++c) {
        float2 w2 = make_float2(wv[c], wv[c]);
        acc[c][0] = ffma2(r0, w2, acc[c][0]);
        acc[c][1] = ffma2(r1, w2, acc[c][1]);
        acc[c][2] = ffma2(r2, w2, acc[c][2]);
        acc[c][3] = ffma2(r3, w2, acc[c][3]);
    }
}

// ---------------------------------------------------------------------------
// 8-col x 8-row GEMM k-slice, ping-pong register pipeline (no copies).
// Buffer A holds k-rows {4t, 4t+1}, buffer B holds {4t+2, 4t+3}; loads for
// the next 4-row group are interleaved between the compute blocks. Outer
// loop NOT unrolled (keeps the pipeline live in SASS — R10 lesson).
// partBase[colg*68 + c*8 + m] += sum over k in [k0, k0+CNT).
// ---------------------------------------------------------------------------
template<int LD, int CNT>
__device__ __forceinline__ void gemm8col(const float* __restrict__ A,
                                         const float* __restrict__ W,
                                         int colg, int k0,
                                         float* __restrict__ partBase)
{
    const float* Wp = W + (size_t)k0 * LD + colg * 8;
    const float* Ap = A + k0 * 8;

    float2 acc[8][4];
#pragma unroll
    for (int c = 0; c < 8; ++c)
#pragma unroll
        for (int p = 0; p < 4; ++p) acc[c][p] = make_float2(0.f, 0.f);

    constexpr int NP = CNT / 2;              // 2-row pairs (even for all uses)
    static_assert(NP >= 4 && (NP % 2) == 0, "pipeline needs >=4 even pairs");

    // prologue: rows 0,1 -> A regs ; rows 2,3 -> B regs
    float4 a0 = ld4(Wp),              a1 = ld4(Wp + 4);
    float4 a2 = ld4(Wp + LD),         a3 = ld4(Wp + LD + 4);
    float4 b0 = ld4(Wp + 2 * LD),     b1 = ld4(Wp + 2 * LD + 4);
    float4 b2 = ld4(Wp + 3 * LD),     b3 = ld4(Wp + 3 * LD + 4);

    const float* Wl = Wp + 4 * (size_t)LD;   // next rows to load
    const float* Al = Ap;                    // rows being computed

#pragma unroll 1
    for (int p = 0; p < NP - 2; p += 2) {
        fma8x1(acc, Al,      a0, a1);        // row 2p
        fma8x1(acc, Al + 8,  a2, a3);        // row 2p+1
        a0 = ld4(Wl);          a1 = ld4(Wl + 4);
        a2 = ld4(Wl + LD);     a3 = ld4(Wl + LD + 4);
        fma8x1(acc, Al + 16, b0, b1);        // row 2p+2
        fma8x1(acc, Al + 24, b2, b3);        // row 2p+3
        b0 = ld4(Wl + 2 * LD); b1 = ld4(Wl + 2 * LD + 4);
        b2 = ld4(Wl + 3 * LD); b3 = ld4(Wl + 3 * LD + 4);
        Wl += 4 * (size_t)LD;
        Al += 32;
    }
    // epilogue: last 4 even rows
    fma8x1(acc, Al,      a0, a1);
    fma8x1(acc, Al + 8,  a2, a3);
    fma8x1(acc, Al + 16, b0, b1);
    fma8x1(acc, Al + 24, b2, b3);

    if constexpr (CNT & 1) {                 // remainder row (CNT=33)
        const int k = CNT - 1;
        float4 wl = ld4(Wp + (size_t)k * LD);
        float4 wh = ld4(Wp + (size_t)k * LD + 4);
        fma8x1(acc, Ap + k * 8, wl, wh);
    }

    float* pp = partBase + colg * 68;
#pragma unroll
    for (int c = 0; c < 8; ++c) {
        *reinterpret_cast<float4*>(pp + c * 8) =
            make_float4(acc[c][0].x, acc[c][0].y, acc[c][1].x, acc[c][1].y);
        *reinterpret_cast<float4*>(pp + c * 8 + 4) =
            make_float4(acc[c][2].x, acc[c][2].y, acc[c][3].x, acc[c][3].y);
    }
}

// Combine 16 padded partials (stride P16) + bias -> C[2048]. 512 thr x float4.
__device__ __forceinline__ void combine16(const float* __restrict__ bias,
                                          float* __restrict__ C)
{
    const int i = threadIdx.x;
    const int base = (i >> 4) * 68 + (i & 15) * 4;
    float4 s = *reinterpret_cast<const float4*>(pool + base);
#pragma unroll
    for (int o = 1; o < 16; ++o) {
        float4 q = *reinterpret_cast<const float4*>(pool + o * P16 + base);
        s.x += q.x; s.y += q.y; s.z += q.z; s.w += q.w;
    }
    float bv = bias[i >> 1];
    s.x += bv; s.y += bv; s.z += bv; s.w += bv;
    *reinterpret_cast<float4*>(C + i * 4) = s;
}

// Combine 8 padded partials (stride P8) + bias + tanh -> C[4096]. 8 elem/thr.
__device__ __forceinline__ void combine8_tanh(const float* __restrict__ bias,
                                              float* __restrict__ C)
{
    const int tid = threadIdx.x;
    const int base = (tid >> 3) * 68 + (tid & 7) * 8;
    float bv = bias[tid];
    float4 s0 = *reinterpret_cast<const float4*>(pool + base);
    float4 s1 = *reinterpret_cast<const float4*>(pool + base + 4);
#pragma unroll
    for (int o = 1; o < 8; ++o) {
        float4 q0 = *reinterpret_cast<const float4*>(pool + o * P8 + base);
        float4 q1 = *reinterpret_cast<const float4*>(pool + o * P8 + base + 4);
        s0.x += q0.x; s0.y += q0.y; s0.z += q0.z; s0.w += q0.w;
        s1.x += q1.x; s1.y += q1.y; s1.z += q1.z; s1.w += q1.w;
    }
    s0.x = tanhf(s0.x + bv); s0.y = tanhf(s0.y + bv);
    s0.z = tanhf(s0.z + bv); s0.w = tanhf(s0.w + bv);
    s1.x = tanhf(s1.x + bv); s1.y = tanhf(s1.y + bv);
    s1.z = tanhf(s1.z + bv); s1.w = tanhf(s1.w + bv);
    *reinterpret_cast<float4*>(C + tid * 8)     = s0;
    *reinterpret_cast<float4*>(C + tid * 8 + 4) = s1;
}

// ---------------------------------------------------------------------------
// N=512 GEMM for K=33 (encoder input): 2 row-groups x 256 col-threads x 2 cols.
// K tiny, weights L2-hot; tanh+bias fused on output.
// ---------------------------------------------------------------------------
template<int K>
__device__ __forceinline__ void gemm_n512_small(const float* __restrict__ A,
                                                const float* __restrict__ W,
                                                const float* __restrict__ bias,
                                                float* __restrict__ C)
{
    const int tid = threadIdx.x;
    const int g   = tid >> 8;
    const int n0  = (tid & 255) << 1;
    const float* Wp = W + n0;
    const float b0 = bias[n0], b1 = bias[n0 + 1];
    float2 a00 = make_float2(b0, b0), a01 = make_float2(b0, b0);
    float2 a10 = make_float2(b1, b1), a11 = make_float2(b1, b1);

#pragma unroll
    for (int k = 0; k < K; ++k) {
        float2 wp = *reinterpret_cast<const float2*>(Wp + (size_t)k * 512);
        float4 av = ld4(A + k * 8 + 4 * g);
        float2 apA = make_float2(av.x, av.y), apB = make_float2(av.z, av.w);
        float2 w0 = make_float2(wp.x, wp.x), w1 = make_float2(wp.y, wp.y);
        a00 = ffma2(apA, w0, a00); a01 = ffma2(apB, w0, a01);
        a10 = ffma2(apA, w1, a10); a11 = ffma2(apB, w1, a11);
    }
    a00.x = tanhf(a00.x); a00.y = tanhf(a00.y);
    a01.x = tanhf(a01.x); a01.y = tanhf(a01.y);
    a10.x = tanhf(a10.x); a10.y = tanhf(a10.y);
    a11.x = tanhf(a11.x); a11.y = tanhf(a11.y);
    *reinterpret_cast<float2*>(C + n0 * 8 + 4 * g)           = a00;
    *reinterpret_cast<float2*>(C + n0 * 8 + 4 * g + 2)       = a01;
    *reinterpret_cast<float2*>(C + (n0 + 1) * 8 + 4 * g)     = a10;
    *reinterpret_cast<float2*>(C + (n0 + 1) * 8 + 4 * g + 2) = a11;
}

// ---------------------------------------------------------------------------
// Persistent kernel: 128 CTAs x 8 batch rows x 512 threads.
// ---------------------------------------------------------------------------
__global__ __launch_bounds__(NTHR)
void solver_kernel(const float* __restrict__ in0,
                   const float* __restrict__ g1,  const float* __restrict__ be1,
                   const float* __restrict__ w1,  const float* __restrict__ b1,
                   const float* __restrict__ w2,  const float* __restrict__ b2,
                   const float* __restrict__ wu,  const float* __restrict__ bu,
                   const float* __restrict__ g2,  const float* __restrict__ be2,
                   const float* __restrict__ wbeta,
                   const float* __restrict__ wd1, const float* __restrict__ bd1,
                   const float* __restrict__ wd2, const float* __restrict__ bd2,
                   const int*   __restrict__ fix, int nfix,
                   float* __restrict__ out)
{
    __shared__ __align__(16) float x33[33 * 8];      // LN'd encoder input
    __shared__ __align__(16) float buf512[512 * 8];  // h1 / t
    __shared__ __align__(16) float hbuf[256 * 8];    // h / dec2 partials
    __shared__ __align__(16) float ubuf[256 * 8];    // u
    __shared__ __align__(16) float comb[257 * 8];    // [LN2(u), ect]
    __shared__ __align__(16) float win[3 * 8 * 8];   // window ring [phys][n][m]
    __shared__ __align__(16) float ybuf[8 * 8 * 16]; // 16-step output staging

    const int tid  = threadIdx.x;
    const int wid  = tid >> 5, lane = tid & 31;
    const int b_base = blockIdx.x * 8;

    const int f0 = (nfix > 0) ? fix[0] : -1;
    const int f1 = (nfix > 1) ? fix[1] : -1;

    // init window = inputs[:, 0:3, 1:9]
    for (int idx = tid; idx < 192; idx += NTHR) {
        int j = idx / 64, rem = idx % 64, n = rem >> 3, m = rem & 7;
        win[j * 64 + n * 8 + m] = in0[((size_t)(b_base + m) * S_SZ + j) * F_SZ + 1 + n];
    }
    __syncthreads();

    for (int step = 0; step < T_STEPS; ++step) {
        const int i = step + LB_SZ;
        const int r = step % 3;

        // ---- LN1: gamma/beta broadcast over LAST axis (index = lane) ----
        if (wid < 8) {
            const int m = wid;
            for (int j = 0; j < 3; ++j) {
                int t = i - 3 + j;
                float v = 0.f;
                if (lane < 11) {
                    if (lane < 3) {
                        size_t base = ((size_t)(b_base + m) * S_SZ + t) * F_SZ;
                        float L = in0[base];
                        if (lane < 2) v = L;                      // loading, cumsum
                        else v = (t > 0) ? (L - in0[base - F_SZ]) : 0.f;
                    } else {
                        v = win[((r + j) % 3) * 64 + (lane - 3) * 8 + m];
                    }
                }
                float s = v, s2 = v * v;
#pragma unroll
                for (int off = 16; off > 0; off >>= 1) {
                    s  += __shfl_xor_sync(0xffffffffu, s,  off);
                    s2 += __shfl_xor_sync(0xffffffffu, s2, off);
                }
                float mean = s * (1.f / 11.f);
                float var  = s2 * (1.f / 11.f) - mean * mean;
                float rs   = rsqrtf(var + LN_EPS);
                if (lane < 11)
                    x33[(j * 11 + lane) * 8 + m] = (v - mean) * rs * g1[lane] + be1[lane];
            }
        }
        __syncthreads();

        gemm_n512_small<33>(x33, w1, b1, buf512);          // h1 = tanh(x@w1+b1)
        __syncthreads();

        // ---- enc2: h = h1@w2 + b2, N=256 K=512, 16-way k-split x 8 cols ----
        {
            const int slice = tid >> 5, colg = tid & 31;
            gemm8col<256, 32>(buf512, w2, colg, slice * 32, pool + slice * P16);
        }
        __syncthreads();
        combine16(b2, hbuf);
        __syncthreads();

        // ---- upd: u = h@wu + bu, N=256 K=256, 16-way k-split x 8 cols ----
        {
            const int slice = tid >> 5, colg = tid & 31;
            gemm8col<256, 16>(hbuf, wu, colg, slice * 16, pool + slice * P16);
        }
        __syncthreads();
        combine16(bu, ubuf);
        __syncthreads();

        // ---- LN2(u) + ect = h@beta_w -> comb[257][8] ----
        if (wid < 8) {
            const int m = wid;
            float uv[8];
            float su = 0.f, sq = 0.f, se = 0.f;
#pragma unroll
            for (int q = 0; q < 8; ++q) {
                int n = lane + 32 * q;
                float x = ubuf[n * 8 + m];
                uv[q] = x; su += x; sq += x * x;
                se += hbuf[n * 8 + m] * wbeta[n];
            }
#pragma unroll
            for (int off = 16; off > 0; off >>= 1) {
                su += __shfl_xor_sync(0xffffffffu, su, off);
                sq += __shfl_xor_sync(0xffffffffu, sq, off);
                se += __shfl_xor_sync(0xffffffffu, se, off);
            }
            float mean = su * (1.f / 256.f);
            float var  = sq * (1.f / 256.f) - mean * mean;
            float rs   = rsqrtf(var + LN_EPS);
#pragma unroll
            for (int q = 0; q < 8; ++q) {
                int n = lane + 32 * q;
                comb[n * 8 + m] = (uv[q] - mean) * rs * g2[n] + be2[n];
            }
            if (lane == 0) comb[256 * 8 + m] = se;
        }
        __syncthreads();

        // ---- dec1: t = tanh(comb@wd1 + bd1), N=512 K=257, 8-way split x 8 cols ----
        {
            const int slice = tid >> 6, colg = tid & 63;
            if (slice == 0)
                gemm8col<512, 33>(comb, wd1, colg, 0, pool);
            else
                gemm8col<512, 32>(comb, wd1, colg, slice * 32 + 1, pool + slice * P8);
        }
        __syncthreads();
        combine8_tanh(bd1, buf512);
        __syncthreads();

        // ---- dec2: y = t@wd2 + bd2, 8-way k-split, partials in hbuf ----
        {
            const int ks = tid >> 6, nm = tid & 63;
            const int n = nm & 7, m = nm >> 3, k0 = ks * 64;
            float a0 = 0.f, a1 = 0.f;
#pragma unroll 8
            for (int k = 0; k < 64; k += 2) {
                a0 += buf512[(k0 + k)     * 8 + m] * wd2[(k0 + k)     * 8 + n];
                a1 += buf512[(k0 + k + 1) * 8 + m] * wd2[(k0 + k + 1) * 8 + n];
            }
            hbuf[ks * 64 + nm] = a0 + a1;
        }
        __syncthreads();
        if (tid < 64) {
            const int n = tid & 7, m = tid >> 3;
            float acc = bd2[n];
#pragma unroll
            for (int ks = 0; ks < 8; ++ks) acc += hbuf[ks * 64 + tid];
            if (n == f0 || n == f1)
                acc = in0[((size_t)(b_base + m) * S_SZ + (i + 1)) * F_SZ + 1 + n];
            ybuf[(n * 8 + m) * 16 + (step & 15)] = acc;
            win[r * 64 + n * 8 + m] = acc;
        }
        __syncthreads();

        if ((step & 15) == 15 && tid < 64) {
            const int n = tid >> 3, m = tid & 7;
            const float4* src = reinterpret_cast<const float4*>(&ybuf[(n * 8 + m) * 16]);
            float4* dst = reinterpret_cast<float4*>(
                &out[(size_t)n * B_SZ * T_STEPS + (size_t)(b_base + m) * T_STEPS + (step - 15)]);
            dst[0] = src[0]; dst[1] = src[1]; dst[2] = src[2]; dst[3] = src[3];
        }
    }

    // tail flush (T_STEPS % 16 == 12)
    if (tid < 64) {
        const int n = tid >> 3, m = tid & 7;
        const int step0 = (T_STEPS / 16) * 16;
        for (int s2 = 0; s2 < T_STEPS - step0; ++s2)
            out[(size_t)n * B_SZ * T_STEPS + (size_t)(b_base + m) * T_STEPS + step0 + s2]
                = ybuf[(n * 8 + m) * 16 + s2];
    }
}

extern "C" void kernel_launch(void* const* d_in, const int* in_sizes, int n_in,
                              void* d_out, int out_size) {
    const float* in0   = (const float*)d_in[0];
    const float* g1    = (const float*)d_in[1];
    const float* be1   = (const float*)d_in[2];
    const float* w1    = (const float*)d_in[3];
    const float* b1    = (const float*)d_in[4];
    const float* w2    = (const float*)d_in[5];
    const float* b2    = (const float*)d_in[6];
    const float* wu    = (const float*)d_in[7];
    const float* bu    = (const float*)d_in[8];
    const float* g2    = (const float*)d_in[9];
    const float* be2   = (const float*)d_in[10];
    const float* wbeta = (const float*)d_in[11];
    const float* wd1   = (const float*)d_in[12];
    const float* bd1   = (const float*)d_in[13];
    const float* wd2   = (const float*)d_in[14];
    const float* bd2   = (const float*)d_in[15];
    const int*   fix   = (const int*)d_in[16];
    const int    nfix  = in_sizes[16];

    cudaFuncSetAttribute(solver_kernel,
                         cudaFuncAttributeMaxDynamicSharedMemorySize, POOL_BYTES);

    solver_kernel<<<B_SZ / 8, NTHR, POOL_BYTES>>>(
        in0, g1, be1, w1, b1, w2, b2, wu, bu,
        g2, be2, wbeta, wd1, bd1, wd2, bd2,
        fix, nfix, (float*)d_out);
}

// round 13
// speedup vs baseline: 1.0017x; 1.0017x over previous
#include <cuda_runtime.h>
#include <cstring>

#define B_SZ   1024
#define S_SZ   2048
#define F_SZ   9
#define LB_SZ  3
#define T_STEPS 2044   // S - 1 - LB
#define LN_EPS 1e-3f
#define NTHR   512

// Partial pools: col-groups of 8 cols padded to 68 floats (64 data + 4 pad)
// so partial STS.128 lane-stride is 68 words (4 mod 32) -> conflict-free.
#define P16 2176                 // 32 groups * 68  (N=256 GEMMs, 16 slices)
#define P8  4352                 // 64 groups * 68  (N=512 dec1, 8 slices)
#define POOL_FLOATS 34816        // max(16*P16, 8*P8)
#define POOL_BYTES  (POOL_FLOATS * 4)

extern __shared__ float pool[];  // 136 KB dynamic scratch (GEMM partials)

// ---------------------------------------------------------------------------
// Packed fp32x2 FMA (Blackwell FFMA2) — only reachable via PTX fma.rn.f32x2
// ---------------------------------------------------------------------------
__device__ __forceinline__ float2 ffma2(float2 a, float2 b, float2 c) {
    unsigned long long ra, rb, rc, rd;
    memcpy(&ra, &a, 8); memcpy(&rb, &b, 8); memcpy(&rc, &c, 8);
    asm("fma.rn.f32x2 %0, %1, %2, %3;" : "=l"(rd) : "l"(ra), "l"(rb), "l"(rc));
    float2 d; memcpy(&d, &rd, 8);
    return d;
}

__device__ __forceinline__ float4 ld4(const float* p) {
    return *reinterpret_cast<const float4*>(p);
}

// One k-row: 8 cols x 8 rows = 32 FFMA2. Arow = 8 activation floats (SMEM).
__device__ __forceinline__ void fma8x1(float2 (&acc)[8][4],
                                       const float* __restrict__ Arow,
                                       float4 wlo, float4 whi)
{
    float4 aA = ld4(Arow);
    float4 aB = ld4(Arow + 4);
    float2 r0 = make_float2(aA.x, aA.y), r1 = make_float2(aA.z, aA.w);
    float2 r2 = make_float2(aB.x, aB.y), r3 = make_float2(aB.z, aB.w);
    const float wv[8] = { wlo.x, wlo.y, wlo.z, wlo.w,
                          whi.x, whi.y, whi.z, whi.w };
#pragma unroll
    for (int c = 0; c < 8; ++c) {
        float2 w2 = make_float2(wv[c], wv[c]);
        acc[c][0] = ffma2(r0, w2, acc[c][0]);
        acc[c][1] = ffma2(r1, w2, acc[c][1]);
        acc[c][2] = ffma2(r2, w2, acc[c][2]);
        acc[c][3] = ffma2(r3, w2, acc[c][3]);
    }
}

// ---------------------------------------------------------------------------
// 8-col x 8-row GEMM k-slice, 4-buffer rotating register pipeline (no copies).
// Buffers A,B,C,D each hold one k-row of 8 weights. Phase t computes from
// buffer t%4 and immediately reloads it with row t+4 -> load-use distance =
// 3 phases (~96 FFMA2 + 6 LDG), comfortably above L2 latency. Outer loop
// NOT unrolled (R10 lesson: full unroll lets ptxas collapse the pipeline).
// partBase[colg*68 + c*8 + m] = sum over k in [k0, k0+CNT).
// ---------------------------------------------------------------------------
template<int LD, int CNT>
__device__ __forceinline__ void gemm8col(const float* __restrict__ A,
                                         const float* __restrict__ W,
                                         int colg, int k0,
                                         float* __restrict__ partBase)
{
    const float* Wp = W + (size_t)k0 * LD + colg * 8;
    const float* Ap = A + k0 * 8;

    float2 acc[8][4];
#pragma unroll
    for (int c = 0; c < 8; ++c)
#pragma unroll
        for (int p = 0; p < 4; ++p) acc[c][p] = make_float2(0.f, 0.f);

    constexpr int NPH = CNT & ~3;            // 4-phase groups (16 or 32)
    static_assert(NPH >= 8, "pipeline needs >= 8 phases");

    // prologue: rows 0..3 -> A,B,C,D
    float4 a0 = ld4(Wp),              a1 = ld4(Wp + 4);
    float4 b0 = ld4(Wp + LD),         b1 = ld4(Wp + LD + 4);
    float4 c0 = ld4(Wp + 2 * LD),     c1 = ld4(Wp + 2 * LD + 4);
    float4 d0 = ld4(Wp + 3 * LD),     d1 = ld4(Wp + 3 * LD + 4);

    const float* Wl = Wp + 4 * (size_t)LD;   // next rows to load (t+4)
    const float* Al = Ap;                    // rows being computed

#pragma unroll 1
    for (int t = 0; t < NPH - 4; t += 4) {
        fma8x1(acc, Al,      a0, a1);  a0 = ld4(Wl);          a1 = ld4(Wl + 4);
        fma8x1(acc, Al + 8,  b0, b1);  b0 = ld4(Wl + LD);     b1 = ld4(Wl + LD + 4);
        fma8x1(acc, Al + 16, c0, c1);  c0 = ld4(Wl + 2 * LD); c1 = ld4(Wl + 2 * LD + 4);
        fma8x1(acc, Al + 24, d0, d1);  d0 = ld4(Wl + 3 * LD); d1 = ld4(Wl + 3 * LD + 4);
        Wl += 4 * (size_t)LD;
        Al += 32;
    }
    // epilogue: last 4 phases (buffers already loaded)
    fma8x1(acc, Al,      a0, a1);
    fma8x1(acc, Al + 8,  b0, b1);
    fma8x1(acc, Al + 16, c0, c1);
    fma8x1(acc, Al + 24, d0, d1);

    // remainder rows [NPH, CNT) — e.g. the 33rd row of dec1 slice 0
#pragma unroll
    for (int k = NPH; k < CNT; ++k) {
        float4 wl = ld4(Wp + (size_t)k * LD);
        float4 wh = ld4(Wp + (size_t)k * LD + 4);
        fma8x1(acc, Ap + k * 8, wl, wh);
    }

    float* pp = partBase + colg * 68;
#pragma unroll
    for (int c = 0; c < 8; ++c) {
        *reinterpret_cast<float4*>(pp + c * 8) =
            make_float4(acc[c][0].x, acc[c][0].y, acc[c][1].x, acc[c][1].y);
        *reinterpret_cast<float4*>(pp + c * 8 + 4) =
            make_float4(acc[c][2].x, acc[c][2].y, acc[c][3].x, acc[c][3].y);
    }
}

// Combine 16 padded partials (stride P16) + bias -> C[2048]. 512 thr x float4.
__device__ __forceinline__ void combine16(const float* __restrict__ bias,
                                          float* __restrict__ C)
{
    const int i = threadIdx.x;
    const int base = (i >> 4) * 68 + (i & 15) * 4;
    float4 s = *reinterpret_cast<const float4*>(pool + base);
#pragma unroll
    for (int o = 1; o < 16; ++o) {
        float4 q = *reinterpret_cast<const float4*>(pool + o * P16 + base);
        s.x += q.x; s.y += q.y; s.z += q.z; s.w += q.w;
    }
    float bv = bias[i >> 1];
    s.x += bv; s.y += bv; s.z += bv; s.w += bv;
    *reinterpret_cast<float4*>(C + i * 4) = s;
}

// Combine 8 padded partials (stride P8) + bias + tanh -> C[4096]. 8 elem/thr.
__device__ __forceinline__ void combine8_tanh(const float* __restrict__ bias,
                                              float* __restrict__ C)
{
    const int tid = threadIdx.x;
    const int base = (tid >> 3) * 68 + (tid & 7) * 8;
    float bv = bias[tid];
    float4 s0 = *reinterpret_cast<const float4*>(pool + base);
    float4 s1 = *reinterpret_cast<const float4*>(pool + base + 4);
#pragma unroll
    for (int o = 1; o < 8; ++o) {
        float4 q0 = *reinterpret_cast<const float4*>(pool + o * P8 + base);
        float4 q1 = *reinterpret_cast<const float4*>(pool + o * P8 + base + 4);
        s0.x += q0.x; s0.y += q0.y; s0.z += q0.z; s0.w += q0.w;
        s1.x += q1.x; s1.y += q1.y; s1.z += q1.z; s1.w += q1.w;
    }
    s0.x = tanhf(s0.x + bv); s0.y = tanhf(s0.y + bv);
    s0.z = tanhf(s0.z + bv); s0.w = tanhf(s0.w + bv);
    s1.x = tanhf(s1.x + bv); s1.y = tanhf(s1.y + bv);
    s1.z = tanhf(s1.z + bv); s1.w = tanhf(s1.w + bv);
    *reinterpret_cast<float4*>(C + tid * 8)     = s0;
    *reinterpret_cast<float4*>(C + tid * 8 + 4) = s1;
}

// ---------------------------------------------------------------------------
// N=512 GEMM for K=33 (encoder input): 2 row-groups x 256 col-threads x 2 cols.
// K tiny, weights L2-hot; tanh+bias fused on output.
// ---------------------------------------------------------------------------
template<int K>
__device__ __forceinline__ void gemm_n512_small(const float* __restrict__ A,
                                                const float* __restrict__ W,
                                                const float* __restrict__ bias,
                                                float* __restrict__ C)
{
    const int tid = threadIdx.x;
    const int g   = tid >> 8;
    const int n0  = (tid & 255) << 1;
    const float* Wp = W + n0;
    const float b0 = bias[n0], b1 = bias[n0 + 1];
    float2 a00 = make_float2(b0, b0), a01 = make_float2(b0, b0);
    float2 a10 = make_float2(b1, b1), a11 = make_float2(b1, b1);

#pragma unroll
    for (int k = 0; k < K; ++k) {
        float2 wp = *reinterpret_cast<const float2*>(Wp + (size_t)k * 512);
        float4 av = ld4(A + k * 8 + 4 * g);
        float2 apA = make_float2(av.x, av.y), apB = make_float2(av.z, av.w);
        float2 w0 = make_float2(wp.x, wp.x), w1 = make_float2(wp.y, wp.y);
        a00 = ffma2(apA, w0, a00); a01 = ffma2(apB, w0, a01);
        a10 = ffma2(apA, w1, a10); a11 = ffma2(apB, w1, a11);
    }
    a00.x = tanhf(a00.x); a00.y = tanhf(a00.y);
    a01.x = tanhf(a01.x); a01.y = tanhf(a01.y);
    a10.x = tanhf(a10.x); a10.y = tanhf(a10.y);
    a11.x = tanhf(a11.x); a11.y = tanhf(a11.y);
    *reinterpret_cast<float2*>(C + n0 * 8 + 4 * g)           = a00;
    *reinterpret_cast<float2*>(C + n0 * 8 + 4 * g + 2)       = a01;
    *reinterpret_cast<float2*>(C + (n0 + 1) * 8 + 4 * g)     = a10;
    *reinterpret_cast<float2*>(C + (n0 + 1) * 8 + 4 * g + 2) = a11;
}

// ---------------------------------------------------------------------------
// Persistent kernel: 128 CTAs x 8 batch rows x 512 threads.
// ---------------------------------------------------------------------------
__global__ __launch_bounds__(NTHR)
void solver_kernel(const float* __restrict__ in0,
                   const float* __restrict__ g1,  const float* __restrict__ be1,
                   const float* __restrict__ w1,  const float* __restrict__ b1,
                   const float* __restrict__ w2,  const float* __restrict__ b2,
                   const float* __restrict__ wu,  const float* __restrict__ bu,
                   const float* __restrict__ g2,  const float* __restrict__ be2,
                   const float* __restrict__ wbeta,
                   const float* __restrict__ wd1, const float* __restrict__ bd1,
                   const float* __restrict__ wd2, const float* __restrict__ bd2,
                   const int*   __restrict__ fix, int nfix,
                   float* __restrict__ out)
{
    __shared__ __align__(16) float x33[33 * 8];      // LN'd encoder input
    __shared__ __align__(16) float buf512[512 * 8];  // h1 / t
    __shared__ __align__(16) float hbuf[256 * 8];    // h / dec2 partials
    __shared__ __align__(16) float ubuf[256 * 8];    // u
    __shared__ __align__(16) float comb[257 * 8];    // [LN2(u), ect]
    __shared__ __align__(16) float win[3 * 8 * 8];   // window ring [phys][n][m]
    __shared__ __align__(16) float ybuf[8 * 8 * 16]; // 16-step output staging

    const int tid  = threadIdx.x;
    const int wid  = tid >> 5, lane = tid & 31;
    const int b_base = blockIdx.x * 8;

    const int f0 = (nfix > 0) ? fix[0] : -1;
    const int f1 = (nfix > 1) ? fix[1] : -1;

    // init window = inputs[:, 0:3, 1:9]
    for (int idx = tid; idx < 192; idx += NTHR) {
        int j = idx / 64, rem = idx % 64, n = rem >> 3, m = rem & 7;
        win[j * 64 + n * 8 + m] = in0[((size_t)(b_base + m) * S_SZ + j) * F_SZ + 1 + n];
    }
    __syncthreads();

    for (int step = 0; step < T_STEPS; ++step) {
        const int i = step + LB_SZ;
        const int r = step % 3;

        // ---- LN1: gamma/beta broadcast over LAST axis (index = lane) ----
        if (wid < 8) {
            const int m = wid;
            for (int j = 0; j < 3; ++j) {
                int t = i - 3 + j;
                float v = 0.f;
                if (lane < 11) {
                    if (lane < 3) {
                        size_t base = ((size_t)(b_base + m) * S_SZ + t) * F_SZ;
                        float L = in0[base];
                        if (lane < 2) v = L;                      // loading, cumsum
                        else v = (t > 0) ? (L - in0[base - F_SZ]) : 0.f;
                    } else {
                        v = win[((r + j) % 3) * 64 + (lane - 3) * 8 + m];
                    }
                }
                float s = v, s2 = v * v;
#pragma unroll
                for (int off = 16; off > 0; off >>= 1) {
                    s  += __shfl_xor_sync(0xffffffffu, s,  off);
                    s2 += __shfl_xor_sync(0xffffffffu, s2, off);
                }
                float mean = s * (1.f / 11.f);
                float var  = s2 * (1.f / 11.f) - mean * mean;
                float rs   = rsqrtf(var + LN_EPS);
                if (lane < 11)
                    x33[(j * 11 + lane) * 8 + m] = (v - mean) * rs * g1[lane] + be1[lane];
            }
        }
        __syncthreads();

        gemm_n512_small<33>(x33, w1, b1, buf512);          // h1 = tanh(x@w1+b1)
        __syncthreads();

        // ---- enc2: h = h1@w2 + b2, N=256 K=512, 16-way k-split x 8 cols ----
        {
            const int slice = tid >> 5, colg = tid & 31;
            gemm8col<256, 32>(buf512, w2, colg, slice * 32, pool + slice * P16);
        }
        __syncthreads();
        combine16(b2, hbuf);
        __syncthreads();

        // ---- upd: u = h@wu + bu, N=256 K=256, 16-way k-split x 8 cols ----
        {
            const int slice = tid >> 5, colg = tid & 31;
            gemm8col<256, 16>(hbuf, wu, colg, slice * 16, pool + slice * P16);
        }
        __syncthreads();
        combine16(bu, ubuf);
        __syncthreads();

        // ---- LN2(u) + ect = h@beta_w -> comb[257][8] ----
        if (wid < 8) {
            const int m = wid;
            float uv[8];
            float su = 0.f, sq = 0.f, se = 0.f;
#pragma unroll
            for (int q = 0; q < 8; ++q) {
                int n = lane + 32 * q;
                float x = ubuf[n * 8 + m];
                uv[q] = x; su += x; sq += x * x;
                se += hbuf[n * 8 + m] * wbeta[n];
            }
#pragma unroll
            for (int off = 16; off > 0; off >>= 1) {
                su += __shfl_xor_sync(0xffffffffu, su, off);
                sq += __shfl_xor_sync(0xffffffffu, sq, off);
                se += __shfl_xor_sync(0xffffffffu, se, off);
            }
            float mean = su * (1.f / 256.f);
            float var  = sq * (1.f / 256.f) - mean * mean;
            float rs   = rsqrtf(var + LN_EPS);
#pragma unroll
            for (int q = 0; q < 8; ++q) {
                int n = lane + 32 * q;
                comb[n * 8 + m] = (uv[q] - mean) * rs * g2[n] + be2[n];
            }
            if (lane == 0) comb[256 * 8 + m] = se;
        }
        __syncthreads();

        // ---- dec1: t = tanh(comb@wd1 + bd1), N=512 K=257, 8-way split x 8 cols ----
        {
            const int slice = tid >> 6, colg = tid & 63;
            if (slice == 0)
                gemm8col<512, 33>(comb, wd1, colg, 0, pool);
            else
                gemm8col<512, 32>(comb, wd1, colg, slice * 32 + 1, pool + slice * P8);
        }
        __syncthreads();
        combine8_tanh(bd1, buf512);
        __syncthreads();

        // ---- dec2: y = t@wd2 + bd2, 8-way k-split, partials in hbuf ----
        {
            const int ks = tid >> 6, nm = tid & 63;
            const int n = nm & 7, m = nm >> 3, k0 = ks * 64;
            float a0 = 0.f, a1 = 0.f;
#pragma unroll 8
            for (int k = 0; k < 64; k += 2) {
                a0 += buf512[(k0 + k)     * 8 + m] * wd2[(k0 + k)     * 8 + n];
                a1 += buf512[(k0 + k + 1) * 8 + m] * wd2[(k0 + k + 1) * 8 + n];
            }
            hbuf[ks * 64 + nm] = a0 + a1;
        }
        __syncthreads();
        if (tid < 64) {
            const int n = tid & 7, m = tid >> 3;
            float acc = bd2[n];
#pragma unroll
            for (int ks = 0; ks < 8; ++ks) acc += hbuf[ks * 64 + tid];
            if (n == f0 || n == f1)
                acc = in0[((size_t)(b_base + m) * S_SZ + (i + 1)) * F_SZ + 1 + n];
            ybuf[(n * 8 + m) * 16 + (step & 15)] = acc;
            win[r * 64 + n * 8 + m] = acc;
        }
        __syncthreads();

        if ((step & 15) == 15 && tid < 64) {
            const int n = tid >> 3, m = tid & 7;
            const float4* src = reinterpret_cast<const float4*>(&ybuf[(n * 8 + m) * 16]);
            float4* dst = reinterpret_cast<float4*>(
                &out[(size_t)n * B_SZ * T_STEPS + (size_t)(b_base + m) * T_STEPS + (step - 15)]);
            dst[0] = src[0]; dst[1] = src[1]; dst[2] = src[2]; dst[3] = src[3];
        }
    }

    // tail flush (T_STEPS % 16 == 12)
    if (tid < 64) {
        const int n = tid >> 3, m = tid & 7;
        const int step0 = (T_STEPS / 16) * 16;
        for (int s2 = 0; s2 < T_STEPS - step0; ++s2)
            out[(size_t)n * B_SZ * T_STEPS + (size_t)(b_base + m) * T_STEPS + step0 + s2]
                = ybuf[(n * 8 + m) * 16 + s2];
    }
}

extern "C" void kernel_launch(void* const* d_in, const int* in_sizes, int n_in,
                              void* d_out, int out_size) {
    const float* in0   = (const float*)d_in[0];
    const float* g1    = (const float*)d_in[1];
    const float* be1   = (const float*)d_in[2];
    const float* w1    = (const float*)d_in[3];
    const float* b1    = (const float*)d_in[4];
    const float* w2    = (const float*)d_in[5];
    const float* b2    = (const float*)d_in[6];
    const float* wu    = (const float*)d_in[7];
    const float* bu    = (const float*)d_in[8];
    const float* g2    = (const float*)d_in[9];
    const float* be2   = (const float*)d_in[10];
    const float* wbeta = (const float*)d_in[11];
    const float* wd1   = (const float*)d_in[12];
    const float* bd1   = (const float*)d_in[13];
    const float* wd2   = (const float*)d_in[14];
    const float* bd2   = (const float*)d_in[15];
    const int*   fix   = (const int*)d_in[16];
    const int    nfix  = in_sizes[16];

    cudaFuncSetAttribute(solver_kernel,
                         cudaFuncAttributeMaxDynamicSharedMemorySize, POOL_BYTES);

    solver_kernel<<<B_SZ / 8, NTHR, POOL_BYTES>>>(
        in0, g1, be1, w1, b1, w2, b2, wu, bu,
        g2, be2, wbeta, wd1, bd1, wd2, bd2,
        fix, nfix, (float*)d_out);
}

// round 14
// speedup vs baseline: 1.0060x; 1.0042x over previous
#include <cuda_runtime.h>
#include <cstring>

#define B_SZ   1024
#define S_SZ   2048
#define F_SZ   9
#define LB_SZ  3
#define T_STEPS 2044   // S - 1 - LB
#define LN_EPS 1e-3f
#define NTHR   512

// Partial pools: col-groups of 8 cols padded to 68 floats (64 data + 4 pad)
// so partial STS.128 lane-stride is 68 words (4 mod 32) -> conflict-free.
#define P16 2176                 // 32 groups * 68  (N=256 GEMMs, 16 slices)
#define P8  4352                 // 64 groups * 68  (N=512 dec1, 8 slices)
#define POOL_FLOATS 34816        // max(16*P16, 8*P8)
#define POOL_BYTES  (POOL_FLOATS * 4)

extern __shared__ float pool[];  // 136 KB dynamic scratch (GEMM partials)

// ---------------------------------------------------------------------------
// Packed fp32x2 FMA (Blackwell FFMA2) — only reachable via PTX fma.rn.f32x2
// ---------------------------------------------------------------------------
__device__ __forceinline__ float2 ffma2(float2 a, float2 b, float2 c) {
    unsigned long long ra, rb, rc, rd;
    memcpy(&ra, &a, 8); memcpy(&rb, &b, 8); memcpy(&rc, &c, 8);
    asm("fma.rn.f32x2 %0, %1, %2, %3;" : "=l"(rd) : "l"(ra), "l"(rb), "l"(rc));
    float2 d; memcpy(&d, &rd, 8);
    return d;
}

__device__ __forceinline__ float4 ld4(const float* p) {
    return *reinterpret_cast<const float4*>(p);
}

// fast tanh: (e^{2x}-1)/(e^{2x}+1) via ex2.approx + rcp.approx (~1e-6 err)
__device__ __forceinline__ float fast_tanh(float x) {
    float cx = fminf(fmaxf(x, -9.f), 9.f);
    float t;
    asm("ex2.approx.f32 %0, %1;" : "=f"(t) : "f"(cx * 2.885390082f)); // 2/ln2
    float r;
    asm("rcp.approx.f32 %0, %1;" : "=f"(r) : "f"(t + 1.f));
    return (t - 1.f) * r;
}

// ---------------------------------------------------------------------------
// 8-col x 8-row GEMM k-slice, UB=2 register prefetch WITH copies — the R11
// shape, empirically the fastest (R12/13 ping-pong variants were slower).
// partBase[colg*68 + c*8 + m] = sum over k in [k0, k0+CNT).
// ---------------------------------------------------------------------------
template<int LD, int CNT>
__device__ __forceinline__ void gemm8col(const float* __restrict__ A,
                                         const float* __restrict__ W,
                                         int colg, int k0,
                                         float* __restrict__ partBase)
{
    const float* Wp = W + (size_t)k0 * LD + colg * 8;
    const float* Ap = A + k0 * 8;

    float2 acc[8][4];
#pragma unroll
    for (int c = 0; c < 8; ++c)
#pragma unroll
        for (int p = 0; p < 4; ++p) acc[c][p] = make_float2(0.f, 0.f);

    constexpr int UB = 2;
    constexpr int NB = CNT / UB;

    float4 wlo[UB], whi[UB];
#pragma unroll
    for (int u = 0; u < UB; ++u) {
        wlo[u] = ld4(Wp + (size_t)u * LD);
        whi[u] = ld4(Wp + (size_t)u * LD + 4);
    }

#pragma unroll 1
    for (int kb = 0; kb < NB - 1; ++kb) {
        float4 nlo[UB], nhi[UB];
        const float* Wn = Wp + (size_t)(kb + 1) * UB * LD;
#pragma unroll
        for (int u = 0; u < UB; ++u) {
            nlo[u] = ld4(Wn + (size_t)u * LD);
            nhi[u] = ld4(Wn + (size_t)u * LD + 4);
        }
#pragma unroll
        for (int u = 0; u < UB; ++u) {
            const int k = kb * UB + u;
            float4 aA = ld4(Ap + k * 8);
            float4 aB = ld4(Ap + k * 8 + 4);
            float2 r0 = make_float2(aA.x, aA.y), r1 = make_float2(aA.z, aA.w);
            float2 r2 = make_float2(aB.x, aB.y), r3 = make_float2(aB.z, aB.w);
            const float wv[8] = { wlo[u].x, wlo[u].y, wlo[u].z, wlo[u].w,
                                  whi[u].x, whi[u].y, whi[u].z, whi[u].w };
#pragma unroll
            for (int c = 0; c < 8; ++c) {
                float2 w2 = make_float2(wv[c], wv[c]);
                acc[c][0] = ffma2(r0, w2, acc[c][0]);
                acc[c][1] = ffma2(r1, w2, acc[c][1]);
                acc[c][2] = ffma2(r2, w2, acc[c][2]);
                acc[c][3] = ffma2(r3, w2, acc[c][3]);
            }
        }
#pragma unroll
        for (int u = 0; u < UB; ++u) { wlo[u] = nlo[u]; whi[u] = nhi[u]; }
    }
#pragma unroll
    for (int u = 0; u < UB; ++u) {
        const int k = (NB - 1) * UB + u;
        float4 aA = ld4(Ap + k * 8);
        float4 aB = ld4(Ap + k * 8 + 4);
        float2 r0 = make_float2(aA.x, aA.y), r1 = make_float2(aA.z, aA.w);
        float2 r2 = make_float2(aB.x, aB.y), r3 = make_float2(aB.z, aB.w);
        const float wv[8] = { wlo[u].x, wlo[u].y, wlo[u].z, wlo[u].w,
                              whi[u].x, whi[u].y, whi[u].z, whi[u].w };
#pragma unroll
        for (int c = 0; c < 8; ++c) {
            float2 w2 = make_float2(wv[c], wv[c]);
            acc[c][0] = ffma2(r0, w2, acc[c][0]);
            acc[c][1] = ffma2(r1, w2, acc[c][1]);
            acc[c][2] = ffma2(r2, w2, acc[c][2]);
            acc[c][3] = ffma2(r3, w2, acc[c][3]);
        }
    }
    // remainder (CNT % UB, e.g. 1 for CNT=33)
#pragma unroll
    for (int k = NB * UB; k < CNT; ++k) {
        float4 wl = ld4(Wp + (size_t)k * LD);
        float4 wh = ld4(Wp + (size_t)k * LD + 4);
        float4 aA = ld4(Ap + k * 8);
        float4 aB = ld4(Ap + k * 8 + 4);
        float2 r0 = make_float2(aA.x, aA.y), r1 = make_float2(aA.z, aA.w);
        float2 r2 = make_float2(aB.x, aB.y), r3 = make_float2(aB.z, aB.w);
        const float wv[8] = { wl.x, wl.y, wl.z, wl.w, wh.x, wh.y, wh.z, wh.w };
#pragma unroll
        for (int c = 0; c < 8; ++c) {
            float2 w2 = make_float2(wv[c], wv[c]);
            acc[c][0] = ffma2(r0, w2, acc[c][0]);
            acc[c][1] = ffma2(r1, w2, acc[c][1]);
            acc[c][2] = ffma2(r2, w2, acc[c][2]);
            acc[c][3] = ffma2(r3, w2, acc[c][3]);
        }
    }

    float* pp = partBase + colg * 68;
#pragma unroll
    for (int c = 0; c < 8; ++c) {
        *reinterpret_cast<float4*>(pp + c * 8) =
            make_float4(acc[c][0].x, acc[c][0].y, acc[c][1].x, acc[c][1].y);
        *reinterpret_cast<float4*>(pp + c * 8 + 4) =
            make_float4(acc[c][2].x, acc[c][2].y, acc[c][3].x, acc[c][3].y);
    }
}

// Combine 16 padded partials (stride P16) + bias -> C[2048]. 512 thr x float4.
__device__ __forceinline__ void combine16(const float* __restrict__ bias,
                                          float* __restrict__ C)
{
    const int i = threadIdx.x;
    const int base = (i >> 4) * 68 + (i & 15) * 4;
    float4 s = *reinterpret_cast<const float4*>(pool + base);
#pragma unroll
    for (int o = 1; o < 16; ++o) {
        float4 q = *reinterpret_cast<const float4*>(pool + o * P16 + base);
        s.x += q.x; s.y += q.y; s.z += q.z; s.w += q.w;
    }
    float bv = bias[i >> 1];
    s.x += bv; s.y += bv; s.z += bv; s.w += bv;
    *reinterpret_cast<float4*>(C + i * 4) = s;
}

// Combine 8 padded partials (stride P8) + bias + fast_tanh -> C[4096].
__device__ __forceinline__ void combine8_tanh(const float* __restrict__ bias,
                                              float* __restrict__ C)
{
    const int tid = threadIdx.x;
    const int base = (tid >> 3) * 68 + (tid & 7) * 8;
    float bv = bias[tid];
    float4 s0 = *reinterpret_cast<const float4*>(pool + base);
    float4 s1 = *reinterpret_cast<const float4*>(pool + base + 4);
#pragma unroll
    for (int o = 1; o < 8; ++o) {
        float4 q0 = *reinterpret_cast<const float4*>(pool + o * P8 + base);
        float4 q1 = *reinterpret_cast<const float4*>(pool + o * P8 + base + 4);
        s0.x += q0.x; s0.y += q0.y; s0.z += q0.z; s0.w += q0.w;
        s1.x += q1.x; s1.y += q1.y; s1.z += q1.z; s1.w += q1.w;
    }
    s0.x = fast_tanh(s0.x + bv); s0.y = fast_tanh(s0.y + bv);
    s0.z = fast_tanh(s0.z + bv); s0.w = fast_tanh(s0.w + bv);
    s1.x = fast_tanh(s1.x + bv); s1.y = fast_tanh(s1.y + bv);
    s1.z = fast_tanh(s1.z + bv); s1.w = fast_tanh(s1.w + bv);
    *reinterpret_cast<float4*>(C + tid * 8)     = s0;
    *reinterpret_cast<float4*>(C + tid * 8 + 4) = s1;
}

// ---------------------------------------------------------------------------
// enc1 GEMM: C[512][8] = tanh(x @ w1 + b1), x read from the 3-slot LN'd ring.
// Chunk j (weight rows j*11..j*11+10) pairs with ring slot (step+j)%3.
// ---------------------------------------------------------------------------
__device__ __forceinline__ void gemm_enc1(const float* __restrict__ xring,
                                          int step,
                                          const float* __restrict__ W,
                                          const float* __restrict__ bias,
                                          float* __restrict__ C)
{
    const int tid = threadIdx.x;
    const int g   = tid >> 8;
    const int n0  = (tid & 255) << 1;
    const float* Wp = W + n0;
    const float b0 = bias[n0], b1 = bias[n0 + 1];
    float2 a00 = make_float2(b0, b0), a01 = make_float2(b0, b0);
    float2 a10 = make_float2(b1, b1), a11 = make_float2(b1, b1);

    const int s0 = step % 3, s1 = (step + 1) % 3, s2 = (step + 2) % 3;
    const float* Abase[3] = { xring + s0 * 88, xring + s1 * 88, xring + s2 * 88 };

#pragma unroll
    for (int j = 0; j < 3; ++j) {
        const float* A = Abase[j];
#pragma unroll
        for (int c = 0; c < 11; ++c) {
            const int k = j * 11 + c;
            float2 wp = *reinterpret_cast<const float2*>(Wp + (size_t)k * 512);
            float4 av = ld4(A + c * 8 + 4 * g);
            float2 apA = make_float2(av.x, av.y), apB = make_float2(av.z, av.w);
            float2 w0 = make_float2(wp.x, wp.x), w1 = make_float2(wp.y, wp.y);
            a00 = ffma2(apA, w0, a00); a01 = ffma2(apB, w0, a01);
            a10 = ffma2(apA, w1, a10); a11 = ffma2(apB, w1, a11);
        }
    }
    a00.x = fast_tanh(a00.x); a00.y = fast_tanh(a00.y);
    a01.x = fast_tanh(a01.x); a01.y = fast_tanh(a01.y);
    a10.x = fast_tanh(a10.x); a10.y = fast_tanh(a10.y);
    a11.x = fast_tanh(a11.x); a11.y = fast_tanh(a11.y);
    *reinterpret_cast<float2*>(C + n0 * 8 + 4 * g)           = a00;
    *reinterpret_cast<float2*>(C + n0 * 8 + 4 * g + 2)       = a01;
    *reinterpret_cast<float2*>(C + (n0 + 1) * 8 + 4 * g)     = a10;
    *reinterpret_cast<float2*>(C + (n0 + 1) * 8 + 4 * g + 2) = a11;
}

// ---------------------------------------------------------------------------
// Persistent kernel: 128 CTAs x 8 batch rows x 512 threads.
// ---------------------------------------------------------------------------
__global__ __launch_bounds__(NTHR)
void solver_kernel(const float* __restrict__ in0,
                   const float* __restrict__ g1,  const float* __restrict__ be1,
                   const float* __restrict__ w1,  const float* __restrict__ b1,
                   const float* __restrict__ w2,  const float* __restrict__ b2,
                   const float* __restrict__ wu,  const float* __restrict__ bu,
                   const float* __restrict__ g2,  const float* __restrict__ be2,
                   const float* __restrict__ wbeta,
                   const float* __restrict__ wd1, const float* __restrict__ bd1,
                   const float* __restrict__ wd2, const float* __restrict__ bd2,
                   const int*   __restrict__ fix, int nfix,
                   float* __restrict__ out)
{
    __shared__ __align__(16) float xring[3 * 88];    // LN'd x rows, slot = t%3
    __shared__ __align__(16) float buf512[512 * 8];  // h1 / t
    __shared__ __align__(16) float hbuf[256 * 8];    // h / dec2 partials
    __shared__ __align__(16) float comb[257 * 8];    // [LN2(u), ect]
    __shared__ __align__(16) float win[3 * 8 * 8];   // window ring, slot = t%3
    __shared__ __align__(16) float ybuf[8 * 8 * 16]; // 16-step output staging

    const int tid  = threadIdx.x;
    const int wid  = tid >> 5, lane = tid & 31;
    const int b_base = blockIdx.x * 8;

    const int f0 = (nfix > 0) ? fix[0] : -1;
    const int f1 = (nfix > 1) ? fix[1] : -1;

    // init window = inputs[:, 0:3, 1:9]  (row t -> slot t%3 = t for t=0..2)
    for (int idx = tid; idx < 192; idx += NTHR) {
        int j = idx / 64, rem = idx % 64, n = rem >> 3, m = rem & 7;
        win[j * 64 + n * 8 + m] = in0[((size_t)(b_base + m) * S_SZ + j) * F_SZ + 1 + n];
    }
    __syncthreads();

    for (int step = 0; step < T_STEPS; ++step) {
        const int i = step + LB_SZ;
        const int r = step % 3;   // win slot for this step's y (time i -> i%3 = r)

        // ---- LN1: only the NEW row t = step+2 (warmup: all 3) ----
        // x-row for absolute time t is step-invariant -> 3-slot ring by t%3.
        if (wid < 8) {
            const int m = wid;
            const int jstart = (step == 0) ? 0 : 2;
            for (int j = jstart; j < 3; ++j) {
                const int t = step + j;
                float v = 0.f;
                if (lane < 11) {
                    if (lane < 3) {
                        size_t base = ((size_t)(b_base + m) * S_SZ + t) * F_SZ;
                        float L = in0[base];
                        if (lane < 2) v = L;                      // loading, cumsum
                        else v = (t > 0) ? (L - in0[base - F_SZ]) : 0.f;
                    } else {
                        v = win[(t % 3) * 64 + (lane - 3) * 8 + m];
                    }
                }
                float s = v, s2 = v * v;
#pragma unroll
                for (int off = 16; off > 0; off >>= 1) {
                    s  += __shfl_xor_sync(0xffffffffu, s,  off);
                    s2 += __shfl_xor_sync(0xffffffffu, s2, off);
                }
                float mean = s * (1.f / 11.f);
                float var  = s2 * (1.f / 11.f) - mean * mean;
                float rs   = rsqrtf(var + LN_EPS);
                if (lane < 11)
                    xring[(t % 3) * 88 + lane * 8 + m] =
                        (v - mean) * rs * g1[lane] + be1[lane];
            }
        }
        __syncthreads();

        gemm_enc1(xring, step, w1, b1, buf512);            // h1 = tanh(x@w1+b1)
        __syncthreads();

        // ---- enc2: h = h1@w2 + b2, N=256 K=512, 16-way k-split x 8 cols ----
        {
            const int slice = tid >> 5, colg = tid & 31;
            gemm8col<256, 32>(buf512, w2, colg, slice * 32, pool + slice * P16);
        }
        __syncthreads();
        combine16(b2, hbuf);
        __syncthreads();

        // ---- upd: u = h@wu + bu partials, 16-way k-split x 8 cols ----
        {
            const int slice = tid >> 5, colg = tid & 31;
            gemm8col<256, 16>(hbuf, wu, colg, slice * 16, pool + slice * P16);
        }
        __syncthreads();

        // ---- fused combine + LN2(u) + ect = h@beta_w -> comb[257][8] ----
        if (wid < 8) {
            const int m = wid;
            float uv[8];
            float su = 0.f, sq = 0.f, se = 0.f;
#pragma unroll
            for (int q = 0; q < 8; ++q) {
                int n = lane + 32 * q;
                int pb = (n >> 3) * 68 + (n & 7) * 8 + m;
                float u = bu[n];
#pragma unroll
                for (int o = 0; o < 16; ++o) u += pool[o * P16 + pb];
                uv[q] = u; su += u; sq += u * u;
                se += hbuf[n * 8 + m] * wbeta[n];
            }
#pragma unroll
            for (int off = 16; off > 0; off >>= 1) {
                su += __shfl_xor_sync(0xffffffffu, su, off);
                sq += __shfl_xor_sync(0xffffffffu, sq, off);
                se += __shfl_xor_sync(0xffffffffu, se, off);
            }
            float mean = su * (1.f / 256.f);
            float var  = sq * (1.f / 256.f) - mean * mean;
            float rs   = rsqrtf(var + LN_EPS);
#pragma unroll
            for (int q = 0; q < 8; ++q) {
                int n = lane + 32 * q;
                comb[n * 8 + m] = (uv[q] - mean) * rs * g2[n] + be2[n];
            }
            if (lane == 0) comb[256 * 8 + m] = se;
        }
        __syncthreads();

        // ---- dec1: t = tanh(comb@wd1 + bd1), N=512 K=257, 8-way split ----
        {
            const int slice = tid >> 6, colg = tid & 63;
            if (slice == 0)
                gemm8col<512, 33>(comb, wd1, colg, 0, pool);
            else
                gemm8col<512, 32>(comb, wd1, colg, slice * 32 + 1, pool + slice * P8);
        }
        __syncthreads();
        combine8_tanh(bd1, buf512);
        __syncthreads();

        // ---- dec2: y = t@wd2 + bd2, 8-way k-split, partials in hbuf ----
        {
            const int ks = tid >> 6, nm = tid & 63;
            const int n = nm & 7, m = nm >> 3, k0 = ks * 64;
            float a0 = 0.f, a1 = 0.f;
#pragma unroll 8
            for (int k = 0; k < 64; k += 2) {
                a0 += buf512[(k0 + k)     * 8 + m] * wd2[(k0 + k)     * 8 + n];
                a1 += buf512[(k0 + k + 1) * 8 + m] * wd2[(k0 + k + 1) * 8 + n];
            }
            hbuf[ks * 64 + nm] = a0 + a1;
        }
        __syncthreads();
        if (tid < 64) {
            const int n = tid & 7, m = tid >> 3;
            float acc = bd2[n];
#pragma unroll
            for (int ks = 0; ks < 8; ++ks) acc += hbuf[ks * 64 + tid];
            if (n == f0 || n == f1)
                acc = in0[((size_t)(b_base + m) * S_SZ + (i + 1)) * F_SZ + 1 + n];
            ybuf[(n * 8 + m) * 16 + (step & 15)] = acc;
            win[r * 64 + n * 8 + m] = acc;
            // flush own ybuf row (same thread wrote all 16 slots -> no barrier)
            if ((step & 15) == 15) {
                const float4* src = reinterpret_cast<const float4*>(&ybuf[(n * 8 + m) * 16]);
                float4* dst = reinterpret_cast<float4*>(
                    &out[(size_t)n * B_SZ * T_STEPS + (size_t)(b_base + m) * T_STEPS + (step - 15)]);
                dst[0] = src[0]; dst[1] = src[1]; dst[2] = src[2]; dst[3] = src[3];
            }
        }
        __syncthreads();
    }

    // tail flush (T_STEPS % 16 == 12): each thread flushes its own row
    if (tid < 64) {
        const int n = tid & 7, m = tid >> 3;
        const int step0 = (T_STEPS / 16) * 16;
        for (int s2 = 0; s2 < T_STEPS - step0; ++s2)
            out[(size_t)n * B_SZ * T_STEPS + (size_t)(b_base + m) * T_STEPS + step0 + s2]
                = ybuf[(n * 8 + m) * 16 + s2];
    }
}

extern "C" void kernel_launch(void* const* d_in, const int* in_sizes, int n_in,
                              void* d_out, int out_size) {
    const float* in0   = (const float*)d_in[0];
    const float* g1    = (const float*)d_in[1];
    const float* be1   = (const float*)d_in[2];
    const float* w1    = (const float*)d_in[3];
    const float* b1    = (const float*)d_in[4];
    const float* w2    = (const float*)d_in[5];
    const float* b2    = (const float*)d_in[6];
    const float* wu    = (const float*)d_in[7];
    const float* bu    = (const float*)d_in[8];
    const float* g2    = (const float*)d_in[9];
    const float* be2   = (const float*)d_in[10];
    const float* wbeta = (const float*)d_in[11];
    const float* wd1   = (const float*)d_in[12];
    const float* bd1   = (const float*)d_in[13];
    const float* wd2   = (const float*)d_in[14];
    const float* bd2   = (const float*)d_in[15];
    const int*   fix   = (const int*)d_in[16];
    const int    nfix  = in_sizes[16];

    cudaFuncSetAttribute(solver_kernel,
                         cudaFuncAttributeMaxDynamicSharedMemorySize, POOL_BYTES);

    solver_kernel<<<B_SZ / 8, NTHR, POOL_BYTES>>>(
        in0, g1, be1, w1, b1, w2, b2, wu, bu,
        g2, be2, wbeta, wd1, bd1, wd2, bd2,
        fix, nfix, (float*)d_out);
}